// round 15
// baseline (speedup 1.0000x reference)
#include <cuda_runtime.h>
#include <cuda_fp16.h>
#include <cstdint>

// ---------------------------------------------------------------------------
// SlidingWindowTransformer: B=4,S=512,D=256,W=32,L=4,H=8,DH=32,DFF=1024,NOUT=32
// Round 15 (= Round 14 resubmit; prior bench was an infra failure):
//  - Persistent GEMM (grid=296=148SMx2): kills wave quantization.
//  - ADDRES epilogue: o-proj/FFN2 add the residual in-epilogue; ln_only after.
// Structure otherwise = R13 (layer-0 factorized, layer-3 compact, fp16 chain).
// ---------------------------------------------------------------------------

namespace {
constexpr int Dm   = 256;
constexpr int DFF  = 1024;
constexpr int NWIN = 2048;            // B*S
constexpr int NTOK = NWIN * 32;       // 65536
constexpr float EPS   = 1e-5f;
constexpr float SCALE = 0.17677669529663687f;  // 32^-0.5
constexpr int TILEB = 18432;          // 128 rows x 144B (BK=64 fp16, padded)
constexpr int STAGE = 2 * TILEB;
constexpr int GSMEM = 2 * STAGE;      // 73728 B; 2 CTAs/SM
constexpr int PGRID = 296;            // persistent grid = 148 SMs x 2 CTAs
}

// fp32 scratch
__device__ float g_pq[32 * 768];               // pos @ Win^T (layer 0)
// fp16 scratch
__device__ __half g_qkv[(size_t)NTOK * 768];   // qkv (l1,2) / kv N=512 (l3) / T (l0)
__device__ __half g_tmp[(size_t)NTOK * Dm];
__device__ __half g_xh [(size_t)NTOK * Dm];    // residual base + GEMM input
__device__ __half g_xq [(size_t)NWIN * Dm];    // compact w=31 copy of x2 (l3 Q in)
__device__ __half g_qc [(size_t)NWIN * Dm];    // l3 Q gemm out
__device__ __half g_xc [(size_t)NWIN * Dm];    // l3 compact activations
__device__ __half g_ah [(size_t)NTOK * Dm];
__device__ __half g_fh [(size_t)NTOK * DFF];
__device__ __half g_xf [(size_t)NWIN * Dm];    // X flat fp16 (layer-0 T gemm)
// fp16 weights
__device__ __half g_winh[4 * 768 * 256];
__device__ __half g_woh [4 * 256 * 256];
__device__ __half g_w1h [4 * 1024 * 256];
__device__ __half g_w2h [4 * 256 * 1024];

// ---------------------------------------------------------------------------
// helpers
// ---------------------------------------------------------------------------
__device__ __forceinline__ void ldsm4(uint32_t* r, uint32_t addr) {
    asm volatile("ldmatrix.sync.aligned.m8n8.x4.shared.b16 {%0,%1,%2,%3}, [%4];"
                 : "=r"(r[0]), "=r"(r[1]), "=r"(r[2]), "=r"(r[3]) : "r"(addr));
}
__device__ __forceinline__ void mma16816(float* c, const uint32_t* a,
                                         uint32_t b0, uint32_t b1) {
    asm volatile(
        "mma.sync.aligned.m16n8k16.row.col.f32.f16.f16.f32 "
        "{%0,%1,%2,%3}, {%4,%5,%6,%7}, {%8,%9}, {%0,%1,%2,%3};"
        : "+f"(c[0]), "+f"(c[1]), "+f"(c[2]), "+f"(c[3])
        : "r"(a[0]), "r"(a[1]), "r"(a[2]), "r"(a[3]), "r"(b0), "r"(b1));
}
__device__ __forceinline__ void cp_async16(uint32_t dst, const void* src) {
    asm volatile("cp.async.cg.shared.global [%0], [%1], 16;"
                 :: "r"(dst), "l"(src) : "memory");
}
__device__ __forceinline__ uint32_t cvt2h(float x, float y) {
    __half2 t{__float2half(x), __float2half(y)};
    return *reinterpret_cast<uint32_t*>(&t);
}
__device__ __forceinline__ void unpack8(uint4 u, float* f) {
    const __half2* hp = reinterpret_cast<const __half2*>(&u);
#pragma unroll
    for (int i = 0; i < 4; i++) {
        float2 t = __half22float2(hp[i]);
        f[i * 2] = t.x; f[i * 2 + 1] = t.y;
    }
}

// ---------------------------------------------------------------------------
// Single prep launch: all weights + X flat -> fp16
// ---------------------------------------------------------------------------
__global__ void prep_all(const float* __restrict__ w_in,
                         const float* __restrict__ w_o,
                         const float* __restrict__ w1,
                         const float* __restrict__ w2,
                         const float* __restrict__ X) {
    int i = blockIdx.x * 256 + threadIdx.x;
    const int S0 = 4 * 768 * 256, S1 = 4 * 256 * 256;
    const int S2 = 4 * 1024 * 256, S3 = 4 * 256 * 1024, S4 = NWIN * 256;
    if (i < S0) { g_winh[i] = __float2half(w_in[i]); return; }
    i -= S0;
    if (i < S1) { g_woh[i] = __float2half(w_o[i]); return; }
    i -= S1;
    if (i < S2) { g_w1h[i] = __float2half(w1[i]); return; }
    i -= S2;
    if (i < S3) { g_w2h[i] = __float2half(w2[i]); return; }
    i -= S3;
    if (i < S4) { g_xf[i] = __float2half(X[i]); }
}

// pos @ Win^T (fp32, 32x768)
__global__ void pq_kernel(const float* __restrict__ pos,
                          const float* __restrict__ w_in) {
    int idx = blockIdx.x * 256 + threadIdx.x;
    if (idx >= 32 * 768) return;
    int w = idx / 768, c = idx % 768;
    const float* pr = pos + w * 256;
    const float* wr = w_in + (size_t)c * 256;
    float s = 0.f;
#pragma unroll 8
    for (int d = 0; d < 256; d++) s = fmaf(pr[d], wr[d], s);
    g_pq[idx] = s;
}

// ---------------------------------------------------------------------------
// Persistent GEMM (NT): C = A @ B^T + bias [+ residual] [ReLU], fp16 out.
// CTA 128x128 tile, BK=64, 8 warps (2Mx4N, 64x32), 2-stage cp.async.
// ---------------------------------------------------------------------------
template <bool RELU, bool ADDRES>
__global__ void __launch_bounds__(256, 2) mma_gemm8(
    const __half* __restrict__ Ah, const __half* __restrict__ Bh,
    const float* __restrict__ bias, const __half* __restrict__ Res,
    __half* __restrict__ Ch, int K, int N, int gx, int ntiles)
{
    extern __shared__ char smem[];
    const uint32_t sb0 = (uint32_t)__cvta_generic_to_shared(smem);

    const int tid  = threadIdx.x;
    const int lane = tid & 31;
    const int wid  = tid >> 5;
    const int m0   = (wid >> 2) * 64;
    const int n0   = (wid & 3) * 32;

    const int lrow = lane & 15;
    const int lch  = lane >> 4;
    uint32_t aOff[4], bOff[2];
#pragma unroll
    for (int i = 0; i < 4; i++)
        aOff[i] = (uint32_t)((m0 + i * 16 + lrow) * 144 + lch * 16);
#pragma unroll
    for (int i = 0; i < 2; i++)
        bOff[i] = (uint32_t)((n0 + i * 16 + lrow) * 144 + lch * 16) + (uint32_t)TILEB;

    const int ntile_k = K >> 6;

    for (int t = blockIdx.x; t < ntiles; t += PGRID) {
        const int bm = (t / gx) * 128;
        const int bn = (t % gx) * 128;

        float c[4][4][4];
#pragma unroll
        for (int i = 0; i < 4; i++)
#pragma unroll
            for (int j = 0; j < 4; j++)
#pragma unroll
                for (int k = 0; k < 4; k++) c[i][j][k] = 0.f;

        auto load_stage = [&](int s, int k0) {
            uint32_t base = sb0 + s * STAGE;
#pragma unroll
            for (int i = 0; i < 8; i++) {
                int cc   = tid + i * 256;
                int isB  = cc >> 10;
                int wi   = cc & 1023;
                int row  = wi >> 3;
                int kc   = wi & 7;
                uint32_t d = base + (uint32_t)(isB * TILEB + row * 144 + kc * 16);
                const __half* src = isB
                    ? (Bh + (size_t)(bn + row) * K + k0 + kc * 8)
                    : (Ah + (size_t)(bm + row) * K + k0 + kc * 8);
                cp_async16(d, src);
            }
            asm volatile("cp.async.commit_group;" ::: "memory");
        };

        load_stage(0, 0);
        for (int it = 0; it < ntile_k; it++) {
            if (it + 1 < ntile_k) {
                load_stage((it + 1) & 1, (it + 1) * 64);
                asm volatile("cp.async.wait_group 1;" ::: "memory");
            } else {
                asm volatile("cp.async.wait_group 0;" ::: "memory");
            }
            __syncthreads();

            uint32_t base = sb0 + (it & 1) * STAGE;
#pragma unroll
            for (int ks = 0; ks < 4; ks++) {
                const uint32_t ko = ks * 32;
                uint32_t a[16], bh[8];
                ldsm4(a + 0,  base + aOff[0] + ko);
                ldsm4(a + 4,  base + aOff[1] + ko);
                ldsm4(a + 8,  base + aOff[2] + ko);
                ldsm4(a + 12, base + aOff[3] + ko);
                ldsm4(bh + 0, base + bOff[0] + ko);
                ldsm4(bh + 4, base + bOff[1] + ko);
#pragma unroll
                for (int mi = 0; mi < 4; mi++)
#pragma unroll
                    for (int j = 0; j < 4; j++) {
                        int g4 = (j >> 1) * 4, jj = j & 1;
                        mma16816(c[mi][j], a + mi * 4, bh[g4 + jj], bh[g4 + 2 + jj]);
                    }
            }
            __syncthreads();
        }

        // epilogue: bias [+residual] [ReLU], fp16 stores
        const int g  = lane >> 2;
        const int t2 = lane & 3;
#pragma unroll
        for (int mi = 0; mi < 4; mi++) {
            int r0 = bm + m0 + mi * 16 + g;
#pragma unroll
            for (int j = 0; j < 4; j++) {
                int col = bn + n0 + j * 8 + t2 * 2;
                float2 bv = *reinterpret_cast<const float2*>(&bias[col]);
                float v0x = c[mi][j][0] + bv.x, v0y = c[mi][j][1] + bv.y;
                float v1x = c[mi][j][2] + bv.x, v1y = c[mi][j][3] + bv.y;
                if (ADDRES) {
                    uint32_t ru0 = *reinterpret_cast<const uint32_t*>(
                        &Res[(size_t)r0 * N + col]);
                    uint32_t ru1 = *reinterpret_cast<const uint32_t*>(
                        &Res[(size_t)(r0 + 8) * N + col]);
                    float2 rf0 = __half22float2(*reinterpret_cast<__half2*>(&ru0));
                    float2 rf1 = __half22float2(*reinterpret_cast<__half2*>(&ru1));
                    v0x += rf0.x; v0y += rf0.y;
                    v1x += rf1.x; v1y += rf1.y;
                }
                if (RELU) {
                    v0x = fmaxf(v0x, 0.f); v0y = fmaxf(v0y, 0.f);
                    v1x = fmaxf(v1x, 0.f); v1y = fmaxf(v1y, 0.f);
                }
                *reinterpret_cast<uint32_t*>(&Ch[(size_t)r0 * N + col]) =
                    cvt2h(v0x, v0y);
                *reinterpret_cast<uint32_t*>(&Ch[(size_t)(r0 + 8) * N + col]) =
                    cvt2h(v1x, v1y);
            }
        }
    }
}

// ---------------------------------------------------------------------------
// Gather: g_xh fp16 (residual base for layer 0)
// ---------------------------------------------------------------------------
__global__ void gather_kernel(const float* __restrict__ X,
                              const float* __restrict__ pos) {
    int idx = blockIdx.x * 256 + threadIdx.x;
    int d4 = idx & 63;
    int w  = (idx >> 6) & 31;
    int n  = idx >> 11;
    int s  = n & 511;
    int b  = n >> 9;
    int src = s - w; if (src < 0) src = 0;
    float4 xv = reinterpret_cast<const float4*>(X)[(size_t)(b * 512 + src) * 64 + d4];
    float4 pv = reinterpret_cast<const float4*>(pos)[(size_t)w * 64 + d4];
    *reinterpret_cast<uint2*>(&g_xh[(size_t)idx * 4]) =
        make_uint2(cvt2h(xv.x + pv.x, xv.y + pv.y),
                   cvt2h(xv.z + pv.z, xv.w + pv.w));
}

// ---------------------------------------------------------------------------
// Attention core (full-output)
// ---------------------------------------------------------------------------
__device__ __forceinline__ void attn_core(
    float (*qs)[36], float (*kT)[36], float (*vs)[36], float (*ps)[36],
    int tid, int bse, int hc, __half* oh)
{
    const int i  = tid >> 2;
    const int jc = tid & 3;

    float q[32];
#pragma unroll
    for (int u = 0; u < 8; u++) {
        float4 t = *reinterpret_cast<const float4*>(&qs[i][u * 4]);
        q[u * 4 + 0] = t.x * SCALE; q[u * 4 + 1] = t.y * SCALE;
        q[u * 4 + 2] = t.z * SCALE; q[u * 4 + 3] = t.w * SCALE;
    }
    float acc[8];
#pragma unroll
    for (int u = 0; u < 8; u++) acc[u] = 0.f;
#pragma unroll
    for (int d = 0; d < 32; d++) {
        float4 k0 = *reinterpret_cast<const float4*>(&kT[d][jc * 8]);
        float4 k1 = *reinterpret_cast<const float4*>(&kT[d][jc * 8 + 4]);
        float qd = q[d];
        acc[0] = fmaf(qd, k0.x, acc[0]); acc[1] = fmaf(qd, k0.y, acc[1]);
        acc[2] = fmaf(qd, k0.z, acc[2]); acc[3] = fmaf(qd, k0.w, acc[3]);
        acc[4] = fmaf(qd, k1.x, acc[4]); acc[5] = fmaf(qd, k1.y, acc[5]);
        acc[6] = fmaf(qd, k1.z, acc[6]); acc[7] = fmaf(qd, k1.w, acc[7]);
    }
    float mx = acc[0];
#pragma unroll
    for (int u = 1; u < 8; u++) mx = fmaxf(mx, acc[u]);
    mx = fmaxf(mx, __shfl_xor_sync(0xffffffffu, mx, 1));
    mx = fmaxf(mx, __shfl_xor_sync(0xffffffffu, mx, 2));
    float sum = 0.f;
#pragma unroll
    for (int u = 0; u < 8; u++) { acc[u] = __expf(acc[u] - mx); sum += acc[u]; }
    sum += __shfl_xor_sync(0xffffffffu, sum, 1);
    sum += __shfl_xor_sync(0xffffffffu, sum, 2);
    float inv = 1.f / sum;
#pragma unroll
    for (int u = 0; u < 8; u++) acc[u] *= inv;
    *reinterpret_cast<float4*>(&ps[i][jc * 8]) =
        make_float4(acc[0], acc[1], acc[2], acc[3]);
    *reinterpret_cast<float4*>(&ps[i][jc * 8 + 4]) =
        make_float4(acc[4], acc[5], acc[6], acc[7]);
    __syncthreads();

    float o[8];
#pragma unroll
    for (int u = 0; u < 8; u++) o[u] = 0.f;
#pragma unroll
    for (int j = 0; j < 32; j++) {
        float pj = ps[i][j];
        float4 v0 = *reinterpret_cast<const float4*>(&vs[j][jc * 8]);
        float4 v1 = *reinterpret_cast<const float4*>(&vs[j][jc * 8 + 4]);
        o[0] = fmaf(pj, v0.x, o[0]); o[1] = fmaf(pj, v0.y, o[1]);
        o[2] = fmaf(pj, v0.z, o[2]); o[3] = fmaf(pj, v0.w, o[3]);
        o[4] = fmaf(pj, v1.x, o[4]); o[5] = fmaf(pj, v1.y, o[5]);
        o[6] = fmaf(pj, v1.z, o[6]); o[7] = fmaf(pj, v1.w, o[7]);
    }
    size_t base = (size_t)(bse + i) * 256 + hc + jc * 8;
    *reinterpret_cast<uint4*>(&oh[base]) =
        make_uint4(cvt2h(o[0], o[1]), cvt2h(o[2], o[3]),
                   cvt2h(o[4], o[5]), cvt2h(o[6], o[7]));
}

// Attention layers 1..2 (full qkv, row stride 768)
__global__ void attn_kernel3(const __half* __restrict__ qkv,
                             __half* __restrict__ oh) {
    __shared__ float qs[32][36];
    __shared__ float kT[32][36];
    __shared__ float vs[32][36];
    __shared__ float ps[32][36];

    const int n   = blockIdx.x >> 3;
    const int h   = blockIdx.x & 7;
    const int tid = threadIdx.x;
    const int bse = n * 32;
    const int hc  = h * 32;

    for (int idx = tid; idx < 384; idx += 128) {
        int c8 = idx & 3;
        int r  = idx >> 2;
        int sect = r >> 5, tok = r & 31;
        uint4 u = *reinterpret_cast<const uint4*>(
            qkv + (size_t)(bse + tok) * 768 + sect * 256 + hc + c8 * 8);
        float f[8];
        unpack8(u, f);
        if (sect == 0) {
#pragma unroll
            for (int i = 0; i < 8; i++) qs[tok][c8 * 8 + i] = f[i];
        } else if (sect == 1) {
#pragma unroll
            for (int i = 0; i < 8; i++) kT[c8 * 8 + i][tok] = f[i];
        } else {
#pragma unroll
            for (int i = 0; i < 8; i++) vs[tok][c8 * 8 + i] = f[i];
        }
    }
    __syncthreads();
    attn_core(qs, kT, vs, ps, tid, bse, hc, oh);
}

// Attention layer 0: qkv[n,w] = T[src(n,w)] + P[w]
__global__ void attn_kernel0(const __half* __restrict__ T,
                             __half* __restrict__ oh) {
    __shared__ float qs[32][36];
    __shared__ float kT[32][36];
    __shared__ float vs[32][36];
    __shared__ float ps[32][36];

    const int n   = blockIdx.x >> 3;
    const int h   = blockIdx.x & 7;
    const int tid = threadIdx.x;
    const int bse = n * 32;
    const int hc  = h * 32;
    const int s   = n & 511;
    const int b   = n >> 9;

    for (int idx = tid; idx < 384; idx += 128) {
        int c8 = idx & 3;
        int r  = idx >> 2;
        int sect = r >> 5, tok = r & 31;
        int src = s - tok; if (src < 0) src = 0;
        size_t off = (size_t)sect * 256 + hc + c8 * 8;
        uint4 u = *reinterpret_cast<const uint4*>(
            T + (size_t)(b * 512 + src) * 768 + off);
        const float* pq = g_pq + (size_t)tok * 768 + off;
        float f[8];
        unpack8(u, f);
#pragma unroll
        for (int i = 0; i < 8; i++) f[i] += pq[i];
        if (sect == 0) {
#pragma unroll
            for (int i = 0; i < 8; i++) qs[tok][c8 * 8 + i] = f[i];
        } else if (sect == 1) {
#pragma unroll
            for (int i = 0; i < 8; i++) kT[c8 * 8 + i][tok] = f[i];
        } else {
#pragma unroll
            for (int i = 0; i < 8; i++) vs[tok][c8 * 8 + i] = f[i];
        }
    }
    __syncthreads();
    attn_core(qs, kT, vs, ps, tid, bse, hc, oh);
}

// Attention layer 3 (minimal): kv = [NTOK x 512], q compact [NWIN x 256].
__global__ void attn_last(const __half* __restrict__ kv,
                          const __half* __restrict__ qc,
                          __half* __restrict__ oh) {
    __shared__ float ks[32][33];
    __shared__ float vs[32][33];
    __shared__ float qrow[32];
    __shared__ float pr[32];

    const int n   = blockIdx.x >> 3;
    const int h   = blockIdx.x & 7;
    const int tid = threadIdx.x;
    const int bse = n * 32;
    const int hc  = h * 32;

    for (int idx = tid; idx < 256; idx += 128) {
        int c8 = idx & 3;
        int r  = idx >> 2;
        int sect = r >> 5, tok = r & 31;
        uint4 u = *reinterpret_cast<const uint4*>(
            kv + (size_t)(bse + tok) * 512 + sect * 256 + hc + c8 * 8);
        float f[8];
        unpack8(u, f);
        float (*dst)[33] = sect ? vs : ks;
#pragma unroll
        for (int i = 0; i < 8; i++) dst[tok][c8 * 8 + i] = f[i];
    }
    if (tid < 32)
        qrow[tid] = __half2float(qc[(size_t)n * 256 + hc + tid]) * SCALE;
    __syncthreads();

    if (tid < 32) {
        float s = 0.f;
#pragma unroll
        for (int d = 0; d < 32; d++) s = fmaf(qrow[d], ks[tid][d], s);
        float mx = s;
#pragma unroll
        for (int o = 16; o > 0; o >>= 1)
            mx = fmaxf(mx, __shfl_xor_sync(0xffffffffu, mx, o));
        float e = __expf(s - mx);
        float sum = e;
#pragma unroll
        for (int o = 16; o > 0; o >>= 1)
            sum += __shfl_xor_sync(0xffffffffu, sum, o);
        pr[tid] = e / sum;
    }
    __syncthreads();

    if (tid < 32) {
        float o = 0.f;
#pragma unroll
        for (int j = 0; j < 32; j++) o = fmaf(pr[j], vs[j][tid], o);
        oh[(size_t)n * 256 + hc + tid] = __float2half(o);
    }
}

// ---------------------------------------------------------------------------
// LayerNorm body
// ---------------------------------------------------------------------------
__device__ __forceinline__ void ln_body(
    const float* vin, const float* gg, const float* bb, int c0, float* r)
{
    float s = 0.f;
#pragma unroll
    for (int j = 0; j < 8; j++) s += vin[j];
#pragma unroll
    for (int o = 16; o > 0; o >>= 1) s += __shfl_xor_sync(0xffffffffu, s, o);
    float mu = s * (1.f / 256.f);
    float s2 = 0.f;
#pragma unroll
    for (int j = 0; j < 8; j++) { float d = vin[j] - mu; s2 += d * d; }
#pragma unroll
    for (int o = 16; o > 0; o >>= 1) s2 += __shfl_xor_sync(0xffffffffu, s2, o);
    float rstd = rsqrtf(s2 * (1.f / 256.f) + EPS);
    float4 g0 = *reinterpret_cast<const float4*>(gg + c0);
    float4 g1 = *reinterpret_cast<const float4*>(gg + c0 + 4);
    float4 b0 = *reinterpret_cast<const float4*>(bb + c0);
    float4 b1 = *reinterpret_cast<const float4*>(bb + c0 + 4);
    r[0] = (vin[0] - mu) * rstd * g0.x + b0.x;
    r[1] = (vin[1] - mu) * rstd * g0.y + b0.y;
    r[2] = (vin[2] - mu) * rstd * g0.z + b0.z;
    r[3] = (vin[3] - mu) * rstd * g0.w + b0.w;
    r[4] = (vin[4] - mu) * rstd * g1.x + b1.x;
    r[5] = (vin[5] - mu) * rstd * g1.y + b1.y;
    r[6] = (vin[6] - mu) * rstd * g1.z + b1.z;
    r[7] = (vin[7] - mu) * rstd * g1.w + b1.w;
}

// LN-only: src holds the pre-LN sum (residual added in GEMM epilogue).
template <bool WRITEQ>
__global__ void ln_only(const __half* __restrict__ src,
                        const float* __restrict__ gg,
                        const float* __restrict__ bb,
                        __half* __restrict__ dst) {
    int warp  = threadIdx.x >> 5;
    int lane  = threadIdx.x & 31;
    int token = blockIdx.x * 8 + warp;
    int c0    = lane * 8;

    uint4 u = *reinterpret_cast<const uint4*>(src + (size_t)token * 256 + c0);
    float v[8];
    unpack8(u, v);
    float r[8];
    ln_body(v, gg, bb, c0, r);
    uint4 o = make_uint4(cvt2h(r[0], r[1]), cvt2h(r[2], r[3]),
                         cvt2h(r[4], r[5]), cvt2h(r[6], r[7]));
    *reinterpret_cast<uint4*>(&dst[(size_t)token * 256 + c0]) = o;
    if (WRITEQ && (token & 31) == 31)
        *reinterpret_cast<uint4*>(&g_xq[(size_t)(token >> 5) * 256 + c0]) = o;
}

// ---------------------------------------------------------------------------
// Head: reads compact fp16 g_xc rows.
// ---------------------------------------------------------------------------
__global__ void head_kernel(const float* __restrict__ hw,
                            const float* __restrict__ hb,
                            float* __restrict__ out) {
    __shared__ float hws[32][257];
    __shared__ float xs[8][256];
    int tid = threadIdx.x;
    for (int idx = tid; idx < 32 * 256; idx += 256) {
        int c = idx >> 8, d = idx & 255;
        hws[c][d] = hw[idx];
    }
    int warp = tid >> 5, lane = tid & 31;
    int n = blockIdx.x * 8 + warp;
    {
        uint4 u = *reinterpret_cast<const uint4*>(
            g_xc + (size_t)n * 256 + lane * 8);
        float f[8];
        unpack8(u, f);
#pragma unroll
        for (int j = 0; j < 8; j++) xs[warp][lane * 8 + j] = f[j];
    }
    __syncthreads();

    float accum = hb[lane];
#pragma unroll 8
    for (int d = 0; d < 256; d++) accum = fmaf(xs[warp][d], hws[lane][d], accum);
    out[(size_t)n * 32 + lane] = accum;
}

// ---------------------------------------------------------------------------
// Launch
// ---------------------------------------------------------------------------
extern "C" void kernel_launch(void* const* d_in, const int* in_sizes, int n_in,
                              void* d_out, int out_size) {
    const float* X    = (const float*)d_in[0];
    const float* pos  = (const float*)d_in[3];
    const float* w_in = (const float*)d_in[4];
    const float* b_in = (const float*)d_in[5];
    const float* w_o  = (const float*)d_in[6];
    const float* b_o  = (const float*)d_in[7];
    const float* w1   = (const float*)d_in[8];
    const float* b1   = (const float*)d_in[9];
    const float* w2   = (const float*)d_in[10];
    const float* b2   = (const float*)d_in[11];
    const float* l1g  = (const float*)d_in[12];
    const float* l1b  = (const float*)d_in[13];
    const float* l2g  = (const float*)d_in[14];
    const float* l2b  = (const float*)d_in[15];
    const float* hw   = (const float*)d_in[16];
    const float* hb   = (const float*)d_in[17];
    float* out = (float*)d_out;

    void* p;
    cudaGetSymbolAddress(&p, g_qkv);  __half* qkv = (__half*)p;
    cudaGetSymbolAddress(&p, g_tmp);  __half* tmp = (__half*)p;
    cudaGetSymbolAddress(&p, g_xh);   __half* xh = (__half*)p;
    cudaGetSymbolAddress(&p, g_xq);   __half* xq = (__half*)p;
    cudaGetSymbolAddress(&p, g_qc);   __half* qc = (__half*)p;
    cudaGetSymbolAddress(&p, g_xc);   __half* xc = (__half*)p;
    cudaGetSymbolAddress(&p, g_ah);   __half* ah = (__half*)p;
    cudaGetSymbolAddress(&p, g_fh);   __half* fh = (__half*)p;
    cudaGetSymbolAddress(&p, g_xf);   __half* xf = (__half*)p;
    cudaGetSymbolAddress(&p, g_winh); __half* winh = (__half*)p;
    cudaGetSymbolAddress(&p, g_woh);  __half* woh = (__half*)p;
    cudaGetSymbolAddress(&p, g_w1h);  __half* w1h = (__half*)p;
    cudaGetSymbolAddress(&p, g_w2h);  __half* w2h = (__half*)p;

    cudaFuncSetAttribute((const void*)mma_gemm8<false, false>,
        cudaFuncAttributeMaxDynamicSharedMemorySize, GSMEM);
    cudaFuncSetAttribute((const void*)mma_gemm8<true, false>,
        cudaFuncAttributeMaxDynamicSharedMemorySize, GSMEM);
    cudaFuncSetAttribute((const void*)mma_gemm8<false, true>,
        cudaFuncAttributeMaxDynamicSharedMemorySize, GSMEM);

    const int PREP_N = 4*768*256 + 4*256*256 + 4*1024*256 + 4*256*1024 + NWIN*256;
    prep_all<<<(PREP_N + 255) / 256, 256>>>(w_in, w_o, w1, w2, X);
    pq_kernel<<<(32 * 768 + 255) / 256, 256>>>(pos, w_in);
    gather_kernel<<<NTOK * 64 / 256, 256>>>(X, pos);

    for (int l = 0; l < 4; l++) {
        if (l == 0) {
            mma_gemm8<false, false><<<PGRID, 256, GSMEM>>>(
                xf, winh, b_in, nullptr, qkv, 256, 768, 6, 96);
            attn_kernel0<<<NWIN * 8, 128>>>(qkv, ah);
        } else if (l < 3) {
            mma_gemm8<false, false><<<PGRID, 256, GSMEM>>>(
                xh, winh + (size_t)l * 768 * 256,
                b_in + (size_t)l * 768, nullptr, qkv, 256, 768, 6, 3072);
            attn_kernel3<<<NWIN * 8, 128>>>(qkv, ah);
        } else {
            mma_gemm8<false, false><<<PGRID, 256, GSMEM>>>(
                xh, winh + (size_t)3 * 768 * 256 + 256 * 256,
                b_in + 3 * 768 + 256, nullptr, qkv, 256, 512, 4, 2048);
            mma_gemm8<false, false><<<PGRID, 256, GSMEM>>>(
                xq, winh + (size_t)3 * 768 * 256,
                b_in + 3 * 768, nullptr, qc, 256, 256, 2, 32);
            attn_last<<<NWIN * 8, 128>>>(qkv, qc, ah);
        }
        if (l < 3) {
            mma_gemm8<false, true><<<PGRID, 256, GSMEM>>>(
                ah, woh + (size_t)l * 256 * 256,
                b_o + (size_t)l * 256, xh, tmp, 256, 256, 2, 1024);
            ln_only<false><<<NTOK / 8, 256>>>(
                tmp, l1g + (size_t)l * 256, l1b + (size_t)l * 256, xh);
            mma_gemm8<true, false><<<PGRID, 256, GSMEM>>>(
                xh, w1h + (size_t)l * 1024 * 256,
                b1 + (size_t)l * 1024, nullptr, fh, 256, 1024, 8, 4096);
            mma_gemm8<false, true><<<PGRID, 256, GSMEM>>>(
                fh, w2h + (size_t)l * 256 * 1024,
                b2 + (size_t)l * 256, xh, tmp, 1024, 256, 2, 1024);
            if (l == 2)
                ln_only<true><<<NTOK / 8, 256>>>(
                    tmp, l2g + (size_t)l * 256, l2b + (size_t)l * 256, xh);
            else
                ln_only<false><<<NTOK / 8, 256>>>(
                    tmp, l2g + (size_t)l * 256, l2b + (size_t)l * 256, xh);
        } else {
            mma_gemm8<false, true><<<PGRID, 256, GSMEM>>>(
                ah, woh + (size_t)3 * 256 * 256,
                b_o + 3 * 256, xq, tmp, 256, 256, 2, 32);
            ln_only<false><<<NWIN / 8, 256>>>(
                tmp, l1g + (size_t)3 * 256, l1b + (size_t)3 * 256, xc);
            mma_gemm8<true, false><<<PGRID, 256, GSMEM>>>(
                xc, w1h + (size_t)3 * 1024 * 256,
                b1 + (size_t)3 * 1024, nullptr, fh, 256, 1024, 8, 128);
            mma_gemm8<false, true><<<PGRID, 256, GSMEM>>>(
                fh, w2h + (size_t)3 * 256 * 1024,
                b2 + 3 * 256, xc, tmp, 1024, 256, 2, 32);
            ln_only<false><<<NWIN / 8, 256>>>(
                tmp, l2g + (size_t)3 * 256, l2b + (size_t)3 * 256, xc);
        }
    }

    head_kernel<<<NWIN / 8, 256>>>(hw, hb, out);
}

// round 16
// speedup vs baseline: 1.0643x; 1.0643x over previous
#include <cuda_runtime.h>
#include <cuda_fp16.h>
#include <cstdint>

// ---------------------------------------------------------------------------
// SlidingWindowTransformer: B=4,S=512,D=256,W=32,L=4,H=8,DH=32,DFF=1024,NOUT=32
// Round 16: R13 structure with the measured-good parts of R15:
//  - per-tile GEMM grids (persistent grid regressed ~150us -> reverted)
//  - ADDRES epilogue + ln_only (kept: saves ~35us; rel_err 8.4e-4 deterministic)
//  - NEW: attention 2 heads per 256-thread block (better fill, fewer blocks)
// ---------------------------------------------------------------------------

namespace {
constexpr int Dm   = 256;
constexpr int DFF  = 1024;
constexpr int NWIN = 2048;            // B*S
constexpr int NTOK = NWIN * 32;       // 65536
constexpr float EPS   = 1e-5f;
constexpr float SCALE = 0.17677669529663687f;  // 32^-0.5
constexpr int TILEB = 18432;          // 128 rows x 144B (BK=64 fp16, padded)
constexpr int STAGE = 2 * TILEB;
constexpr int GSMEM = 2 * STAGE;      // 73728 B; 2 CTAs/SM
}

// fp32 scratch
__device__ float g_pq[32 * 768];               // pos @ Win^T (layer 0)
// fp16 scratch
__device__ __half g_qkv[(size_t)NTOK * 768];   // qkv (l1,2) / kv N=512 (l3) / T (l0)
__device__ __half g_tmp[(size_t)NTOK * Dm];
__device__ __half g_xh [(size_t)NTOK * Dm];    // residual base + GEMM input
__device__ __half g_xq [(size_t)NWIN * Dm];    // compact w=31 copy of x2 (l3 Q in)
__device__ __half g_qc [(size_t)NWIN * Dm];    // l3 Q gemm out
__device__ __half g_xc [(size_t)NWIN * Dm];    // l3 compact activations
__device__ __half g_ah [(size_t)NTOK * Dm];
__device__ __half g_fh [(size_t)NTOK * DFF];
__device__ __half g_xf [(size_t)NWIN * Dm];    // X flat fp16 (layer-0 T gemm)
// fp16 weights
__device__ __half g_winh[4 * 768 * 256];
__device__ __half g_woh [4 * 256 * 256];
__device__ __half g_w1h [4 * 1024 * 256];
__device__ __half g_w2h [4 * 256 * 1024];

// ---------------------------------------------------------------------------
// helpers
// ---------------------------------------------------------------------------
__device__ __forceinline__ void ldsm4(uint32_t* r, uint32_t addr) {
    asm volatile("ldmatrix.sync.aligned.m8n8.x4.shared.b16 {%0,%1,%2,%3}, [%4];"
                 : "=r"(r[0]), "=r"(r[1]), "=r"(r[2]), "=r"(r[3]) : "r"(addr));
}
__device__ __forceinline__ void mma16816(float* c, const uint32_t* a,
                                         uint32_t b0, uint32_t b1) {
    asm volatile(
        "mma.sync.aligned.m16n8k16.row.col.f32.f16.f16.f32 "
        "{%0,%1,%2,%3}, {%4,%5,%6,%7}, {%8,%9}, {%0,%1,%2,%3};"
        : "+f"(c[0]), "+f"(c[1]), "+f"(c[2]), "+f"(c[3])
        : "r"(a[0]), "r"(a[1]), "r"(a[2]), "r"(a[3]), "r"(b0), "r"(b1));
}
__device__ __forceinline__ void cp_async16(uint32_t dst, const void* src) {
    asm volatile("cp.async.cg.shared.global [%0], [%1], 16;"
                 :: "r"(dst), "l"(src) : "memory");
}
__device__ __forceinline__ uint32_t cvt2h(float x, float y) {
    __half2 t{__float2half(x), __float2half(y)};
    return *reinterpret_cast<uint32_t*>(&t);
}
__device__ __forceinline__ void unpack8(uint4 u, float* f) {
    const __half2* hp = reinterpret_cast<const __half2*>(&u);
#pragma unroll
    for (int i = 0; i < 4; i++) {
        float2 t = __half22float2(hp[i]);
        f[i * 2] = t.x; f[i * 2 + 1] = t.y;
    }
}

// ---------------------------------------------------------------------------
// Single prep launch: all weights + X flat -> fp16
// ---------------------------------------------------------------------------
__global__ void prep_all(const float* __restrict__ w_in,
                         const float* __restrict__ w_o,
                         const float* __restrict__ w1,
                         const float* __restrict__ w2,
                         const float* __restrict__ X) {
    int i = blockIdx.x * 256 + threadIdx.x;
    const int S0 = 4 * 768 * 256, S1 = 4 * 256 * 256;
    const int S2 = 4 * 1024 * 256, S3 = 4 * 256 * 1024, S4 = NWIN * 256;
    if (i < S0) { g_winh[i] = __float2half(w_in[i]); return; }
    i -= S0;
    if (i < S1) { g_woh[i] = __float2half(w_o[i]); return; }
    i -= S1;
    if (i < S2) { g_w1h[i] = __float2half(w1[i]); return; }
    i -= S2;
    if (i < S3) { g_w2h[i] = __float2half(w2[i]); return; }
    i -= S3;
    if (i < S4) { g_xf[i] = __float2half(X[i]); }
}

// pos @ Win^T (fp32, 32x768)
__global__ void pq_kernel(const float* __restrict__ pos,
                          const float* __restrict__ w_in) {
    int idx = blockIdx.x * 256 + threadIdx.x;
    if (idx >= 32 * 768) return;
    int w = idx / 768, c = idx % 768;
    const float* pr = pos + w * 256;
    const float* wr = w_in + (size_t)c * 256;
    float s = 0.f;
#pragma unroll 8
    for (int d = 0; d < 256; d++) s = fmaf(pr[d], wr[d], s);
    g_pq[idx] = s;
}

// ---------------------------------------------------------------------------
// GEMM (NT), per-tile grid: C = A @ B^T + bias [+ residual] [ReLU], fp16 out.
// CTA 128x128, BK=64, 8 warps (2Mx4N, 64x32), 2-stage cp.async, 2 CTAs/SM.
// ---------------------------------------------------------------------------
template <bool RELU, bool ADDRES>
__global__ void __launch_bounds__(256, 2) mma_gemm9(
    const __half* __restrict__ Ah, const __half* __restrict__ Bh,
    const float* __restrict__ bias, const __half* __restrict__ Res,
    __half* __restrict__ Ch, int K, int N)
{
    extern __shared__ char smem[];
    const uint32_t sb0 = (uint32_t)__cvta_generic_to_shared(smem);

    const int tid  = threadIdx.x;
    const int lane = tid & 31;
    const int wid  = tid >> 5;
    const int bm   = blockIdx.y * 128;
    const int bn   = blockIdx.x * 128;
    const int m0   = (wid >> 2) * 64;
    const int n0   = (wid & 3) * 32;

    const int lrow = lane & 15;
    const int lch  = lane >> 4;
    uint32_t aOff[4], bOff[2];
#pragma unroll
    for (int i = 0; i < 4; i++)
        aOff[i] = (uint32_t)((m0 + i * 16 + lrow) * 144 + lch * 16);
#pragma unroll
    for (int i = 0; i < 2; i++)
        bOff[i] = (uint32_t)((n0 + i * 16 + lrow) * 144 + lch * 16) + (uint32_t)TILEB;

    float c[4][4][4];
#pragma unroll
    for (int i = 0; i < 4; i++)
#pragma unroll
        for (int j = 0; j < 4; j++)
#pragma unroll
            for (int k = 0; k < 4; k++) c[i][j][k] = 0.f;

    auto load_stage = [&](int s, int k0) {
        uint32_t base = sb0 + s * STAGE;
#pragma unroll
        for (int i = 0; i < 8; i++) {
            int cc   = tid + i * 256;
            int isB  = cc >> 10;
            int wi   = cc & 1023;
            int row  = wi >> 3;
            int kc   = wi & 7;
            uint32_t d = base + (uint32_t)(isB * TILEB + row * 144 + kc * 16);
            const __half* src = isB
                ? (Bh + (size_t)(bn + row) * K + k0 + kc * 8)
                : (Ah + (size_t)(bm + row) * K + k0 + kc * 8);
            cp_async16(d, src);
        }
        asm volatile("cp.async.commit_group;" ::: "memory");
    };

    const int ntile = K >> 6;
    load_stage(0, 0);
    for (int it = 0; it < ntile; it++) {
        if (it + 1 < ntile) {
            load_stage((it + 1) & 1, (it + 1) * 64);
            asm volatile("cp.async.wait_group 1;" ::: "memory");
        } else {
            asm volatile("cp.async.wait_group 0;" ::: "memory");
        }
        __syncthreads();

        uint32_t base = sb0 + (it & 1) * STAGE;
#pragma unroll
        for (int ks = 0; ks < 4; ks++) {
            const uint32_t ko = ks * 32;
            uint32_t a[16], bh[8];
            ldsm4(a + 0,  base + aOff[0] + ko);
            ldsm4(a + 4,  base + aOff[1] + ko);
            ldsm4(a + 8,  base + aOff[2] + ko);
            ldsm4(a + 12, base + aOff[3] + ko);
            ldsm4(bh + 0, base + bOff[0] + ko);
            ldsm4(bh + 4, base + bOff[1] + ko);
#pragma unroll
            for (int mi = 0; mi < 4; mi++)
#pragma unroll
                for (int j = 0; j < 4; j++) {
                    int g4 = (j >> 1) * 4, jj = j & 1;
                    mma16816(c[mi][j], a + mi * 4, bh[g4 + jj], bh[g4 + 2 + jj]);
                }
        }
        __syncthreads();
    }

    // epilogue: bias [+residual] [ReLU], fp16 stores
    const int g  = lane >> 2;
    const int t2 = lane & 3;
#pragma unroll
    for (int mi = 0; mi < 4; mi++) {
        int r0 = bm + m0 + mi * 16 + g;
#pragma unroll
        for (int j = 0; j < 4; j++) {
            int col = bn + n0 + j * 8 + t2 * 2;
            float2 bv = *reinterpret_cast<const float2*>(&bias[col]);
            float v0x = c[mi][j][0] + bv.x, v0y = c[mi][j][1] + bv.y;
            float v1x = c[mi][j][2] + bv.x, v1y = c[mi][j][3] + bv.y;
            if (ADDRES) {
                uint32_t ru0 = *reinterpret_cast<const uint32_t*>(
                    &Res[(size_t)r0 * N + col]);
                uint32_t ru1 = *reinterpret_cast<const uint32_t*>(
                    &Res[(size_t)(r0 + 8) * N + col]);
                float2 rf0 = __half22float2(*reinterpret_cast<__half2*>(&ru0));
                float2 rf1 = __half22float2(*reinterpret_cast<__half2*>(&ru1));
                v0x += rf0.x; v0y += rf0.y;
                v1x += rf1.x; v1y += rf1.y;
            }
            if (RELU) {
                v0x = fmaxf(v0x, 0.f); v0y = fmaxf(v0y, 0.f);
                v1x = fmaxf(v1x, 0.f); v1y = fmaxf(v1y, 0.f);
            }
            *reinterpret_cast<uint32_t*>(&Ch[(size_t)r0 * N + col]) =
                cvt2h(v0x, v0y);
            *reinterpret_cast<uint32_t*>(&Ch[(size_t)(r0 + 8) * N + col]) =
                cvt2h(v1x, v1y);
        }
    }
}

// ---------------------------------------------------------------------------
// Gather: g_xh fp16 (residual base for layer 0)
// ---------------------------------------------------------------------------
__global__ void gather_kernel(const float* __restrict__ X,
                              const float* __restrict__ pos) {
    int idx = blockIdx.x * 256 + threadIdx.x;
    int d4 = idx & 63;
    int w  = (idx >> 6) & 31;
    int n  = idx >> 11;
    int s  = n & 511;
    int b  = n >> 9;
    int src = s - w; if (src < 0) src = 0;
    float4 xv = reinterpret_cast<const float4*>(X)[(size_t)(b * 512 + src) * 64 + d4];
    float4 pv = reinterpret_cast<const float4*>(pos)[(size_t)w * 64 + d4];
    *reinterpret_cast<uint2*>(&g_xh[(size_t)idx * 4]) =
        make_uint2(cvt2h(xv.x + pv.x, xv.y + pv.y),
                   cvt2h(xv.z + pv.z, xv.w + pv.w));
}

// ---------------------------------------------------------------------------
// Attention core: one 128-thread half-block = one (window,head).
// ---------------------------------------------------------------------------
__device__ __forceinline__ void attn_core(
    float (*qs)[36], float (*kT)[36], float (*vs)[36], float (*ps)[36],
    int tl, int bse, int hc, __half* oh)
{
    const int i  = tl >> 2;
    const int jc = tl & 3;

    float q[32];
#pragma unroll
    for (int u = 0; u < 8; u++) {
        float4 t = *reinterpret_cast<const float4*>(&qs[i][u * 4]);
        q[u * 4 + 0] = t.x * SCALE; q[u * 4 + 1] = t.y * SCALE;
        q[u * 4 + 2] = t.z * SCALE; q[u * 4 + 3] = t.w * SCALE;
    }
    float acc[8];
#pragma unroll
    for (int u = 0; u < 8; u++) acc[u] = 0.f;
#pragma unroll
    for (int d = 0; d < 32; d++) {
        float4 k0 = *reinterpret_cast<const float4*>(&kT[d][jc * 8]);
        float4 k1 = *reinterpret_cast<const float4*>(&kT[d][jc * 8 + 4]);
        float qd = q[d];
        acc[0] = fmaf(qd, k0.x, acc[0]); acc[1] = fmaf(qd, k0.y, acc[1]);
        acc[2] = fmaf(qd, k0.z, acc[2]); acc[3] = fmaf(qd, k0.w, acc[3]);
        acc[4] = fmaf(qd, k1.x, acc[4]); acc[5] = fmaf(qd, k1.y, acc[5]);
        acc[6] = fmaf(qd, k1.z, acc[6]); acc[7] = fmaf(qd, k1.w, acc[7]);
    }
    float mx = acc[0];
#pragma unroll
    for (int u = 1; u < 8; u++) mx = fmaxf(mx, acc[u]);
    mx = fmaxf(mx, __shfl_xor_sync(0xffffffffu, mx, 1));
    mx = fmaxf(mx, __shfl_xor_sync(0xffffffffu, mx, 2));
    float sum = 0.f;
#pragma unroll
    for (int u = 0; u < 8; u++) { acc[u] = __expf(acc[u] - mx); sum += acc[u]; }
    sum += __shfl_xor_sync(0xffffffffu, sum, 1);
    sum += __shfl_xor_sync(0xffffffffu, sum, 2);
    float inv = 1.f / sum;
#pragma unroll
    for (int u = 0; u < 8; u++) acc[u] *= inv;
    *reinterpret_cast<float4*>(&ps[i][jc * 8]) =
        make_float4(acc[0], acc[1], acc[2], acc[3]);
    *reinterpret_cast<float4*>(&ps[i][jc * 8 + 4]) =
        make_float4(acc[4], acc[5], acc[6], acc[7]);
    __syncthreads();

    float o[8];
#pragma unroll
    for (int u = 0; u < 8; u++) o[u] = 0.f;
#pragma unroll
    for (int j = 0; j < 32; j++) {
        float pj = ps[i][j];
        float4 v0 = *reinterpret_cast<const float4*>(&vs[j][jc * 8]);
        float4 v1 = *reinterpret_cast<const float4*>(&vs[j][jc * 8 + 4]);
        o[0] = fmaf(pj, v0.x, o[0]); o[1] = fmaf(pj, v0.y, o[1]);
        o[2] = fmaf(pj, v0.z, o[2]); o[3] = fmaf(pj, v0.w, o[3]);
        o[4] = fmaf(pj, v1.x, o[4]); o[5] = fmaf(pj, v1.y, o[5]);
        o[6] = fmaf(pj, v1.z, o[6]); o[7] = fmaf(pj, v1.w, o[7]);
    }
    size_t base = (size_t)(bse + i) * 256 + hc + jc * 8;
    *reinterpret_cast<uint4*>(&oh[base]) =
        make_uint4(cvt2h(o[0], o[1]), cvt2h(o[2], o[3]),
                   cvt2h(o[4], o[5]), cvt2h(o[6], o[7]));
}

// Attention layers 1..2: 256 threads = 2 heads per block. 8192 blocks.
__global__ void attn_kernel3(const __half* __restrict__ qkv,
                             __half* __restrict__ oh) {
    __shared__ float qs[2][32][36];
    __shared__ float kT[2][32][36];
    __shared__ float vs[2][32][36];
    __shared__ float ps[2][32][36];

    const int n   = blockIdx.x >> 2;
    const int h2  = threadIdx.x >> 7;                 // 0/1: head half
    const int h   = ((blockIdx.x & 3) << 1) + h2;
    const int tl  = threadIdx.x & 127;
    const int bse = n * 32;
    const int hc  = h * 32;

    for (int idx = tl; idx < 384; idx += 128) {
        int c8 = idx & 3;
        int r  = idx >> 2;
        int sect = r >> 5, tok = r & 31;
        uint4 u = *reinterpret_cast<const uint4*>(
            qkv + (size_t)(bse + tok) * 768 + sect * 256 + hc + c8 * 8);
        float f[8];
        unpack8(u, f);
        if (sect == 0) {
#pragma unroll
            for (int i = 0; i < 8; i++) qs[h2][tok][c8 * 8 + i] = f[i];
        } else if (sect == 1) {
#pragma unroll
            for (int i = 0; i < 8; i++) kT[h2][c8 * 8 + i][tok] = f[i];
        } else {
#pragma unroll
            for (int i = 0; i < 8; i++) vs[h2][tok][c8 * 8 + i] = f[i];
        }
    }
    __syncthreads();
    attn_core(qs[h2], kT[h2], vs[h2], ps[h2], tl, bse, hc, oh);
}

// Attention layer 0: qkv[n,w] = T[src(n,w)] + P[w]. 2 heads per block.
__global__ void attn_kernel0(const __half* __restrict__ T,
                             __half* __restrict__ oh) {
    __shared__ float qs[2][32][36];
    __shared__ float kT[2][32][36];
    __shared__ float vs[2][32][36];
    __shared__ float ps[2][32][36];

    const int n   = blockIdx.x >> 2;
    const int h2  = threadIdx.x >> 7;
    const int h   = ((blockIdx.x & 3) << 1) + h2;
    const int tl  = threadIdx.x & 127;
    const int bse = n * 32;
    const int hc  = h * 32;
    const int s   = n & 511;
    const int b   = n >> 9;

    for (int idx = tl; idx < 384; idx += 128) {
        int c8 = idx & 3;
        int r  = idx >> 2;
        int sect = r >> 5, tok = r & 31;
        int src = s - tok; if (src < 0) src = 0;
        size_t off = (size_t)sect * 256 + hc + c8 * 8;
        uint4 u = *reinterpret_cast<const uint4*>(
            T + (size_t)(b * 512 + src) * 768 + off);
        const float* pq = g_pq + (size_t)tok * 768 + off;
        float f[8];
        unpack8(u, f);
#pragma unroll
        for (int i = 0; i < 8; i++) f[i] += pq[i];
        if (sect == 0) {
#pragma unroll
            for (int i = 0; i < 8; i++) qs[h2][tok][c8 * 8 + i] = f[i];
        } else if (sect == 1) {
#pragma unroll
            for (int i = 0; i < 8; i++) kT[h2][c8 * 8 + i][tok] = f[i];
        } else {
#pragma unroll
            for (int i = 0; i < 8; i++) vs[h2][tok][c8 * 8 + i] = f[i];
        }
    }
    __syncthreads();
    attn_core(qs[h2], kT[h2], vs[h2], ps[h2], tl, bse, hc, oh);
}

// Attention layer 3 (minimal): kv = [NTOK x 512], q compact [NWIN x 256].
__global__ void attn_last(const __half* __restrict__ kv,
                          const __half* __restrict__ qc,
                          __half* __restrict__ oh) {
    __shared__ float ks[32][33];
    __shared__ float vs[32][33];
    __shared__ float qrow[32];
    __shared__ float pr[32];

    const int n   = blockIdx.x >> 3;
    const int h   = blockIdx.x & 7;
    const int tid = threadIdx.x;
    const int bse = n * 32;
    const int hc  = h * 32;

    for (int idx = tid; idx < 256; idx += 128) {
        int c8 = idx & 3;
        int r  = idx >> 2;
        int sect = r >> 5, tok = r & 31;
        uint4 u = *reinterpret_cast<const uint4*>(
            kv + (size_t)(bse + tok) * 512 + sect * 256 + hc + c8 * 8);
        float f[8];
        unpack8(u, f);
        float (*dst)[33] = sect ? vs : ks;
#pragma unroll
        for (int i = 0; i < 8; i++) dst[tok][c8 * 8 + i] = f[i];
    }
    if (tid < 32)
        qrow[tid] = __half2float(qc[(size_t)n * 256 + hc + tid]) * SCALE;
    __syncthreads();

    if (tid < 32) {
        float s = 0.f;
#pragma unroll
        for (int d = 0; d < 32; d++) s = fmaf(qrow[d], ks[tid][d], s);
        float mx = s;
#pragma unroll
        for (int o = 16; o > 0; o >>= 1)
            mx = fmaxf(mx, __shfl_xor_sync(0xffffffffu, mx, o));
        float e = __expf(s - mx);
        float sum = e;
#pragma unroll
        for (int o = 16; o > 0; o >>= 1)
            sum += __shfl_xor_sync(0xffffffffu, sum, o);
        pr[tid] = e / sum;
    }
    __syncthreads();

    if (tid < 32) {
        float o = 0.f;
#pragma unroll
        for (int j = 0; j < 32; j++) o = fmaf(pr[j], vs[j][tid], o);
        oh[(size_t)n * 256 + hc + tid] = __float2half(o);
    }
}

// ---------------------------------------------------------------------------
// LayerNorm body
// ---------------------------------------------------------------------------
__device__ __forceinline__ void ln_body(
    const float* vin, const float* gg, const float* bb, int c0, float* r)
{
    float s = 0.f;
#pragma unroll
    for (int j = 0; j < 8; j++) s += vin[j];
#pragma unroll
    for (int o = 16; o > 0; o >>= 1) s += __shfl_xor_sync(0xffffffffu, s, o);
    float mu = s * (1.f / 256.f);
    float s2 = 0.f;
#pragma unroll
    for (int j = 0; j < 8; j++) { float d = vin[j] - mu; s2 += d * d; }
#pragma unroll
    for (int o = 16; o > 0; o >>= 1) s2 += __shfl_xor_sync(0xffffffffu, s2, o);
    float rstd = rsqrtf(s2 * (1.f / 256.f) + EPS);
    float4 g0 = *reinterpret_cast<const float4*>(gg + c0);
    float4 g1 = *reinterpret_cast<const float4*>(gg + c0 + 4);
    float4 b0 = *reinterpret_cast<const float4*>(bb + c0);
    float4 b1 = *reinterpret_cast<const float4*>(bb + c0 + 4);
    r[0] = (vin[0] - mu) * rstd * g0.x + b0.x;
    r[1] = (vin[1] - mu) * rstd * g0.y + b0.y;
    r[2] = (vin[2] - mu) * rstd * g0.z + b0.z;
    r[3] = (vin[3] - mu) * rstd * g0.w + b0.w;
    r[4] = (vin[4] - mu) * rstd * g1.x + b1.x;
    r[5] = (vin[5] - mu) * rstd * g1.y + b1.y;
    r[6] = (vin[6] - mu) * rstd * g1.z + b1.z;
    r[7] = (vin[7] - mu) * rstd * g1.w + b1.w;
}

// LN-only: src holds the pre-LN sum (residual added in GEMM epilogue).
template <bool WRITEQ>
__global__ void ln_only(const __half* __restrict__ src,
                        const float* __restrict__ gg,
                        const float* __restrict__ bb,
                        __half* __restrict__ dst) {
    int warp  = threadIdx.x >> 5;
    int lane  = threadIdx.x & 31;
    int token = blockIdx.x * 8 + warp;
    int c0    = lane * 8;

    uint4 u = *reinterpret_cast<const uint4*>(src + (size_t)token * 256 + c0);
    float v[8];
    unpack8(u, v);
    float r[8];
    ln_body(v, gg, bb, c0, r);
    uint4 o = make_uint4(cvt2h(r[0], r[1]), cvt2h(r[2], r[3]),
                         cvt2h(r[4], r[5]), cvt2h(r[6], r[7]));
    *reinterpret_cast<uint4*>(&dst[(size_t)token * 256 + c0]) = o;
    if (WRITEQ && (token & 31) == 31)
        *reinterpret_cast<uint4*>(&g_xq[(size_t)(token >> 5) * 256 + c0]) = o;
}

// ---------------------------------------------------------------------------
// Head: reads compact fp16 g_xc rows.
// ---------------------------------------------------------------------------
__global__ void head_kernel(const float* __restrict__ hw,
                            const float* __restrict__ hb,
                            float* __restrict__ out) {
    __shared__ float hws[32][257];
    __shared__ float xs[8][256];
    int tid = threadIdx.x;
    for (int idx = tid; idx < 32 * 256; idx += 256) {
        int c = idx >> 8, d = idx & 255;
        hws[c][d] = hw[idx];
    }
    int warp = tid >> 5, lane = tid & 31;
    int n = blockIdx.x * 8 + warp;
    {
        uint4 u = *reinterpret_cast<const uint4*>(
            g_xc + (size_t)n * 256 + lane * 8);
        float f[8];
        unpack8(u, f);
#pragma unroll
        for (int j = 0; j < 8; j++) xs[warp][lane * 8 + j] = f[j];
    }
    __syncthreads();

    float accum = hb[lane];
#pragma unroll 8
    for (int d = 0; d < 256; d++) accum = fmaf(xs[warp][d], hws[lane][d], accum);
    out[(size_t)n * 32 + lane] = accum;
}

// ---------------------------------------------------------------------------
// Launch
// ---------------------------------------------------------------------------
extern "C" void kernel_launch(void* const* d_in, const int* in_sizes, int n_in,
                              void* d_out, int out_size) {
    const float* X    = (const float*)d_in[0];
    const float* pos  = (const float*)d_in[3];
    const float* w_in = (const float*)d_in[4];
    const float* b_in = (const float*)d_in[5];
    const float* w_o  = (const float*)d_in[6];
    const float* b_o  = (const float*)d_in[7];
    const float* w1   = (const float*)d_in[8];
    const float* b1   = (const float*)d_in[9];
    const float* w2   = (const float*)d_in[10];
    const float* b2   = (const float*)d_in[11];
    const float* l1g  = (const float*)d_in[12];
    const float* l1b  = (const float*)d_in[13];
    const float* l2g  = (const float*)d_in[14];
    const float* l2b  = (const float*)d_in[15];
    const float* hw   = (const float*)d_in[16];
    const float* hb   = (const float*)d_in[17];
    float* out = (float*)d_out;

    void* p;
    cudaGetSymbolAddress(&p, g_qkv);  __half* qkv = (__half*)p;
    cudaGetSymbolAddress(&p, g_tmp);  __half* tmp = (__half*)p;
    cudaGetSymbolAddress(&p, g_xh);   __half* xh = (__half*)p;
    cudaGetSymbolAddress(&p, g_xq);   __half* xq = (__half*)p;
    cudaGetSymbolAddress(&p, g_qc);   __half* qc = (__half*)p;
    cudaGetSymbolAddress(&p, g_xc);   __half* xc = (__half*)p;
    cudaGetSymbolAddress(&p, g_ah);   __half* ah = (__half*)p;
    cudaGetSymbolAddress(&p, g_fh);   __half* fh = (__half*)p;
    cudaGetSymbolAddress(&p, g_xf);   __half* xf = (__half*)p;
    cudaGetSymbolAddress(&p, g_winh); __half* winh = (__half*)p;
    cudaGetSymbolAddress(&p, g_woh);  __half* woh = (__half*)p;
    cudaGetSymbolAddress(&p, g_w1h);  __half* w1h = (__half*)p;
    cudaGetSymbolAddress(&p, g_w2h);  __half* w2h = (__half*)p;

    cudaFuncSetAttribute((const void*)mma_gemm9<false, false>,
        cudaFuncAttributeMaxDynamicSharedMemorySize, GSMEM);
    cudaFuncSetAttribute((const void*)mma_gemm9<true, false>,
        cudaFuncAttributeMaxDynamicSharedMemorySize, GSMEM);
    cudaFuncSetAttribute((const void*)mma_gemm9<false, true>,
        cudaFuncAttributeMaxDynamicSharedMemorySize, GSMEM);

    const int PREP_N = 4*768*256 + 4*256*256 + 4*1024*256 + 4*256*1024 + NWIN*256;
    prep_all<<<(PREP_N + 255) / 256, 256>>>(w_in, w_o, w1, w2, X);
    pq_kernel<<<(32 * 768 + 255) / 256, 256>>>(pos, w_in);
    gather_kernel<<<NTOK * 64 / 256, 256>>>(X, pos);

    for (int l = 0; l < 4; l++) {
        if (l == 0) {
            mma_gemm9<false, false><<<dim3(6, 16), 256, GSMEM>>>(
                xf, winh, b_in, nullptr, qkv, 256, 768);
            attn_kernel0<<<NWIN * 4, 256>>>(qkv, ah);
        } else if (l < 3) {
            mma_gemm9<false, false><<<dim3(6, 512), 256, GSMEM>>>(
                xh, winh + (size_t)l * 768 * 256,
                b_in + (size_t)l * 768, nullptr, qkv, 256, 768);
            attn_kernel3<<<NWIN * 4, 256>>>(qkv, ah);
        } else {
            mma_gemm9<false, false><<<dim3(4, 512), 256, GSMEM>>>(
                xh, winh + (size_t)3 * 768 * 256 + 256 * 256,
                b_in + 3 * 768 + 256, nullptr, qkv, 256, 512);
            mma_gemm9<false, false><<<dim3(2, 16), 256, GSMEM>>>(
                xq, winh + (size_t)3 * 768 * 256,
                b_in + 3 * 768, nullptr, qc, 256, 256);
            attn_last<<<NWIN * 8, 128>>>(qkv, qc, ah);
        }
        if (l < 3) {
            mma_gemm9<false, true><<<dim3(2, 512), 256, GSMEM>>>(
                ah, woh + (size_t)l * 256 * 256,
                b_o + (size_t)l * 256, xh, tmp, 256, 256);
            ln_only<false><<<NTOK / 8, 256>>>(
                tmp, l1g + (size_t)l * 256, l1b + (size_t)l * 256, xh);
            mma_gemm9<true, false><<<dim3(8, 512), 256, GSMEM>>>(
                xh, w1h + (size_t)l * 1024 * 256,
                b1 + (size_t)l * 1024, nullptr, fh, 256, 1024);
            mma_gemm9<false, true><<<dim3(2, 512), 256, GSMEM>>>(
                fh, w2h + (size_t)l * 256 * 1024,
                b2 + (size_t)l * 256, xh, tmp, 1024, 256);
            if (l == 2)
                ln_only<true><<<NTOK / 8, 256>>>(
                    tmp, l2g + (size_t)l * 256, l2b + (size_t)l * 256, xh);
            else
                ln_only<false><<<NTOK / 8, 256>>>(
                    tmp, l2g + (size_t)l * 256, l2b + (size_t)l * 256, xh);
        } else {
            mma_gemm9<false, true><<<dim3(2, 16), 256, GSMEM>>>(
                ah, woh + (size_t)3 * 256 * 256,
                b_o + 3 * 256, xq, tmp, 256, 256);
            ln_only<false><<<NWIN / 8, 256>>>(
                tmp, l1g + (size_t)3 * 256, l1b + (size_t)3 * 256, xc);
            mma_gemm9<true, false><<<dim3(8, 16), 256, GSMEM>>>(
                xc, w1h + (size_t)3 * 1024 * 256,
                b1 + (size_t)3 * 1024, nullptr, fh, 256, 1024);
            mma_gemm9<false, true><<<dim3(2, 16), 256, GSMEM>>>(
                fh, w2h + (size_t)3 * 256 * 1024,
                b2 + 3 * 256, xc, tmp, 1024, 256);
            ln_only<false><<<NWIN / 8, 256>>>(
                tmp, l2g + (size_t)3 * 256, l2b + (size_t)3 * 256, xc);
        }
    }

    head_kernel<<<NWIN / 8, 256>>>(hw, hb, out);
}

// round 17
// speedup vs baseline: 1.0919x; 1.0260x over previous
#include <cuda_runtime.h>
#include <cuda_fp16.h>
#include <cstdint>

// ---------------------------------------------------------------------------
// SlidingWindowTransformer: B=4,S=512,D=256,W=32,L=4,H=8,DH=32,DFF=1024,NOUT=32
// Round 17: R13 config restored (measured best: add_ln fp32-sum, 128-thread
// attention, per-tile grids; ADDRES/persistence reverted per R15/R16 data)
// + GEMM pipeline deepened to 3 stages at BK=64 (110KB smem, 2 CTAs/SM).
// ---------------------------------------------------------------------------

namespace {
constexpr int Dm   = 256;
constexpr int DFF  = 1024;
constexpr int NWIN = 2048;            // B*S
constexpr int NTOK = NWIN * 32;       // 65536
constexpr float EPS   = 1e-5f;
constexpr float SCALE = 0.17677669529663687f;  // 32^-0.5
constexpr int TILEB = 18432;          // 128 rows x 144B (BK=64 fp16, padded)
constexpr int STAGE = 2 * TILEB;      // A + B = 36864
constexpr int GSMEM = 3 * STAGE;      // 3-stage = 110592 B; 2 CTAs/SM
}

// fp32 scratch
__device__ float g_pq[32 * 768];               // pos @ Win^T (layer 0)
// fp16 scratch
__device__ __half g_qkv[(size_t)NTOK * 768];   // qkv (l1,2) / kv N=512 (l3) / T (l0)
__device__ __half g_tmp[(size_t)NTOK * Dm];
__device__ __half g_xh [(size_t)NTOK * Dm];    // residual base + GEMM input
__device__ __half g_xq [(size_t)NWIN * Dm];    // compact w=31 copy of x2 (l3 Q in)
__device__ __half g_qc [(size_t)NWIN * Dm];    // l3 Q gemm out
__device__ __half g_xc [(size_t)NWIN * Dm];    // l3 compact activations
__device__ __half g_ah [(size_t)NTOK * Dm];
__device__ __half g_fh [(size_t)NTOK * DFF];
__device__ __half g_xf [(size_t)NWIN * Dm];    // X flat fp16 (layer-0 T gemm)
// fp16 weights
__device__ __half g_winh[4 * 768 * 256];
__device__ __half g_woh [4 * 256 * 256];
__device__ __half g_w1h [4 * 1024 * 256];
__device__ __half g_w2h [4 * 256 * 1024];

// ---------------------------------------------------------------------------
// helpers
// ---------------------------------------------------------------------------
__device__ __forceinline__ void ldsm4(uint32_t* r, uint32_t addr) {
    asm volatile("ldmatrix.sync.aligned.m8n8.x4.shared.b16 {%0,%1,%2,%3}, [%4];"
                 : "=r"(r[0]), "=r"(r[1]), "=r"(r[2]), "=r"(r[3]) : "r"(addr));
}
__device__ __forceinline__ void mma16816(float* c, const uint32_t* a,
                                         uint32_t b0, uint32_t b1) {
    asm volatile(
        "mma.sync.aligned.m16n8k16.row.col.f32.f16.f16.f32 "
        "{%0,%1,%2,%3}, {%4,%5,%6,%7}, {%8,%9}, {%0,%1,%2,%3};"
        : "+f"(c[0]), "+f"(c[1]), "+f"(c[2]), "+f"(c[3])
        : "r"(a[0]), "r"(a[1]), "r"(a[2]), "r"(a[3]), "r"(b0), "r"(b1));
}
__device__ __forceinline__ void cp_async16(uint32_t dst, const void* src) {
    asm volatile("cp.async.cg.shared.global [%0], [%1], 16;"
                 :: "r"(dst), "l"(src) : "memory");
}
__device__ __forceinline__ uint32_t cvt2h(float x, float y) {
    __half2 t{__float2half(x), __float2half(y)};
    return *reinterpret_cast<uint32_t*>(&t);
}
__device__ __forceinline__ void unpack8(uint4 u, float* f) {
    const __half2* hp = reinterpret_cast<const __half2*>(&u);
#pragma unroll
    for (int i = 0; i < 4; i++) {
        float2 t = __half22float2(hp[i]);
        f[i * 2] = t.x; f[i * 2 + 1] = t.y;
    }
}

// ---------------------------------------------------------------------------
// Single prep launch: all weights + X flat -> fp16
// ---------------------------------------------------------------------------
__global__ void prep_all(const float* __restrict__ w_in,
                         const float* __restrict__ w_o,
                         const float* __restrict__ w1,
                         const float* __restrict__ w2,
                         const float* __restrict__ X) {
    int i = blockIdx.x * 256 + threadIdx.x;
    const int S0 = 4 * 768 * 256, S1 = 4 * 256 * 256;
    const int S2 = 4 * 1024 * 256, S3 = 4 * 256 * 1024, S4 = NWIN * 256;
    if (i < S0) { g_winh[i] = __float2half(w_in[i]); return; }
    i -= S0;
    if (i < S1) { g_woh[i] = __float2half(w_o[i]); return; }
    i -= S1;
    if (i < S2) { g_w1h[i] = __float2half(w1[i]); return; }
    i -= S2;
    if (i < S3) { g_w2h[i] = __float2half(w2[i]); return; }
    i -= S3;
    if (i < S4) { g_xf[i] = __float2half(X[i]); }
}

// pos @ Win^T (fp32, 32x768)
__global__ void pq_kernel(const float* __restrict__ pos,
                          const float* __restrict__ w_in) {
    int idx = blockIdx.x * 256 + threadIdx.x;
    if (idx >= 32 * 768) return;
    int w = idx / 768, c = idx % 768;
    const float* pr = pos + w * 256;
    const float* wr = w_in + (size_t)c * 256;
    float s = 0.f;
#pragma unroll 8
    for (int d = 0; d < 256; d++) s = fmaf(pr[d], wr[d], s);
    g_pq[idx] = s;
}

// ---------------------------------------------------------------------------
// GEMM (NT): C[M,N] = Ah[M,K] @ Bh[N,K]^T + bias[N], fp16 out, opt ReLU.
// CTA 128x128, BK=64, 8 warps (2Mx4N, 64x32), cp.async 3-stage, 2 CTAs/SM.
// ---------------------------------------------------------------------------
template <bool RELU>
__global__ void __launch_bounds__(256, 2) mma_gemm7(
    const __half* __restrict__ Ah, const __half* __restrict__ Bh,
    const float* __restrict__ bias, __half* __restrict__ Ch,
    int K, int N)
{
    extern __shared__ char smem[];
    const uint32_t sb0 = (uint32_t)__cvta_generic_to_shared(smem);

    const int tid  = threadIdx.x;
    const int lane = tid & 31;
    const int wid  = tid >> 5;
    const int bm   = blockIdx.y * 128;
    const int bn   = blockIdx.x * 128;
    const int m0   = (wid >> 2) * 64;
    const int n0   = (wid & 3) * 32;

    const int lrow = lane & 15;
    const int lch  = lane >> 4;
    uint32_t aOff[4], bOff[2];
#pragma unroll
    for (int i = 0; i < 4; i++)
        aOff[i] = (uint32_t)((m0 + i * 16 + lrow) * 144 + lch * 16);
#pragma unroll
    for (int i = 0; i < 2; i++)
        bOff[i] = (uint32_t)((n0 + i * 16 + lrow) * 144 + lch * 16) + (uint32_t)TILEB;

    float c[4][4][4];
#pragma unroll
    for (int i = 0; i < 4; i++)
#pragma unroll
        for (int j = 0; j < 4; j++)
#pragma unroll
            for (int k = 0; k < 4; k++) c[i][j][k] = 0.f;

    auto load_stage = [&](int s, int k0) {
        uint32_t base = sb0 + s * STAGE;
#pragma unroll
        for (int i = 0; i < 8; i++) {
            int cc   = tid + i * 256;
            int isB  = cc >> 10;
            int wi   = cc & 1023;
            int row  = wi >> 3;
            int kc   = wi & 7;
            uint32_t d = base + (uint32_t)(isB * TILEB + row * 144 + kc * 16);
            const __half* src = isB
                ? (Bh + (size_t)(bn + row) * K + k0 + kc * 8)
                : (Ah + (size_t)(bm + row) * K + k0 + kc * 8);
            cp_async16(d, src);
        }
        asm volatile("cp.async.commit_group;" ::: "memory");
    };

    const int ntile = K >> 6;
    load_stage(0, 0);
    if (ntile > 1) load_stage(1, 64);
    int s = 0;
    for (int it = 0; it < ntile; it++) {
        if (it + 2 < ntile) {
            int s2 = s + 2; if (s2 >= 3) s2 -= 3;
            load_stage(s2, (it + 2) * 64);
            asm volatile("cp.async.wait_group 2;" ::: "memory");
        } else if (it + 1 < ntile) {
            asm volatile("cp.async.wait_group 1;" ::: "memory");
        } else {
            asm volatile("cp.async.wait_group 0;" ::: "memory");
        }
        __syncthreads();

        uint32_t base = sb0 + s * STAGE;
#pragma unroll
        for (int ks = 0; ks < 4; ks++) {
            const uint32_t ko = ks * 32;
            uint32_t a[16], bh[8];
            ldsm4(a + 0,  base + aOff[0] + ko);
            ldsm4(a + 4,  base + aOff[1] + ko);
            ldsm4(a + 8,  base + aOff[2] + ko);
            ldsm4(a + 12, base + aOff[3] + ko);
            ldsm4(bh + 0, base + bOff[0] + ko);
            ldsm4(bh + 4, base + bOff[1] + ko);
#pragma unroll
            for (int mi = 0; mi < 4; mi++)
#pragma unroll
                for (int j = 0; j < 4; j++) {
                    int g4 = (j >> 1) * 4, jj = j & 1;
                    mma16816(c[mi][j], a + mi * 4, bh[g4 + jj], bh[g4 + 2 + jj]);
                }
        }
        __syncthreads();
        s = (s == 2) ? 0 : s + 1;
    }

    const int g  = lane >> 2;
    const int t2 = lane & 3;
#pragma unroll
    for (int mi = 0; mi < 4; mi++) {
        int r0 = bm + m0 + mi * 16 + g;
#pragma unroll
        for (int j = 0; j < 4; j++) {
            int col = bn + n0 + j * 8 + t2 * 2;
            float2 bv = *reinterpret_cast<const float2*>(&bias[col]);
            float v0x = c[mi][j][0] + bv.x, v0y = c[mi][j][1] + bv.y;
            float v1x = c[mi][j][2] + bv.x, v1y = c[mi][j][3] + bv.y;
            if (RELU) {
                v0x = fmaxf(v0x, 0.f); v0y = fmaxf(v0y, 0.f);
                v1x = fmaxf(v1x, 0.f); v1y = fmaxf(v1y, 0.f);
            }
            *reinterpret_cast<uint32_t*>(&Ch[(size_t)r0 * N + col]) =
                cvt2h(v0x, v0y);
            *reinterpret_cast<uint32_t*>(&Ch[(size_t)(r0 + 8) * N + col]) =
                cvt2h(v1x, v1y);
        }
    }
}

// ---------------------------------------------------------------------------
// Gather: g_xh fp16 (residual base for layer 0)
// ---------------------------------------------------------------------------
__global__ void gather_kernel(const float* __restrict__ X,
                              const float* __restrict__ pos) {
    int idx = blockIdx.x * 256 + threadIdx.x;
    int d4 = idx & 63;
    int w  = (idx >> 6) & 31;
    int n  = idx >> 11;
    int s  = n & 511;
    int b  = n >> 9;
    int src = s - w; if (src < 0) src = 0;
    float4 xv = reinterpret_cast<const float4*>(X)[(size_t)(b * 512 + src) * 64 + d4];
    float4 pv = reinterpret_cast<const float4*>(pos)[(size_t)w * 64 + d4];
    *reinterpret_cast<uint2*>(&g_xh[(size_t)idx * 4]) =
        make_uint2(cvt2h(xv.x + pv.x, xv.y + pv.y),
                   cvt2h(xv.z + pv.z, xv.w + pv.w));
}

// ---------------------------------------------------------------------------
// Attention core (full-output)
// ---------------------------------------------------------------------------
__device__ __forceinline__ void attn_core(
    float (*qs)[36], float (*kT)[36], float (*vs)[36], float (*ps)[36],
    int tid, int bse, int hc, __half* oh)
{
    const int i  = tid >> 2;
    const int jc = tid & 3;

    float q[32];
#pragma unroll
    for (int u = 0; u < 8; u++) {
        float4 t = *reinterpret_cast<const float4*>(&qs[i][u * 4]);
        q[u * 4 + 0] = t.x * SCALE; q[u * 4 + 1] = t.y * SCALE;
        q[u * 4 + 2] = t.z * SCALE; q[u * 4 + 3] = t.w * SCALE;
    }
    float acc[8];
#pragma unroll
    for (int u = 0; u < 8; u++) acc[u] = 0.f;
#pragma unroll
    for (int d = 0; d < 32; d++) {
        float4 k0 = *reinterpret_cast<const float4*>(&kT[d][jc * 8]);
        float4 k1 = *reinterpret_cast<const float4*>(&kT[d][jc * 8 + 4]);
        float qd = q[d];
        acc[0] = fmaf(qd, k0.x, acc[0]); acc[1] = fmaf(qd, k0.y, acc[1]);
        acc[2] = fmaf(qd, k0.z, acc[2]); acc[3] = fmaf(qd, k0.w, acc[3]);
        acc[4] = fmaf(qd, k1.x, acc[4]); acc[5] = fmaf(qd, k1.y, acc[5]);
        acc[6] = fmaf(qd, k1.z, acc[6]); acc[7] = fmaf(qd, k1.w, acc[7]);
    }
    float mx = acc[0];
#pragma unroll
    for (int u = 1; u < 8; u++) mx = fmaxf(mx, acc[u]);
    mx = fmaxf(mx, __shfl_xor_sync(0xffffffffu, mx, 1));
    mx = fmaxf(mx, __shfl_xor_sync(0xffffffffu, mx, 2));
    float sum = 0.f;
#pragma unroll
    for (int u = 0; u < 8; u++) { acc[u] = __expf(acc[u] - mx); sum += acc[u]; }
    sum += __shfl_xor_sync(0xffffffffu, sum, 1);
    sum += __shfl_xor_sync(0xffffffffu, sum, 2);
    float inv = 1.f / sum;
#pragma unroll
    for (int u = 0; u < 8; u++) acc[u] *= inv;
    *reinterpret_cast<float4*>(&ps[i][jc * 8]) =
        make_float4(acc[0], acc[1], acc[2], acc[3]);
    *reinterpret_cast<float4*>(&ps[i][jc * 8 + 4]) =
        make_float4(acc[4], acc[5], acc[6], acc[7]);
    __syncthreads();

    float o[8];
#pragma unroll
    for (int u = 0; u < 8; u++) o[u] = 0.f;
#pragma unroll
    for (int j = 0; j < 32; j++) {
        float pj = ps[i][j];
        float4 v0 = *reinterpret_cast<const float4*>(&vs[j][jc * 8]);
        float4 v1 = *reinterpret_cast<const float4*>(&vs[j][jc * 8 + 4]);
        o[0] = fmaf(pj, v0.x, o[0]); o[1] = fmaf(pj, v0.y, o[1]);
        o[2] = fmaf(pj, v0.z, o[2]); o[3] = fmaf(pj, v0.w, o[3]);
        o[4] = fmaf(pj, v1.x, o[4]); o[5] = fmaf(pj, v1.y, o[5]);
        o[6] = fmaf(pj, v1.z, o[6]); o[7] = fmaf(pj, v1.w, o[7]);
    }
    size_t base = (size_t)(bse + i) * 256 + hc + jc * 8;
    *reinterpret_cast<uint4*>(&oh[base]) =
        make_uint4(cvt2h(o[0], o[1]), cvt2h(o[2], o[3]),
                   cvt2h(o[4], o[5]), cvt2h(o[6], o[7]));
}

// Attention layers 1..2 (full qkv, row stride 768)
__global__ void attn_kernel3(const __half* __restrict__ qkv,
                             __half* __restrict__ oh) {
    __shared__ float qs[32][36];
    __shared__ float kT[32][36];
    __shared__ float vs[32][36];
    __shared__ float ps[32][36];

    const int n   = blockIdx.x >> 3;
    const int h   = blockIdx.x & 7;
    const int tid = threadIdx.x;
    const int bse = n * 32;
    const int hc  = h * 32;

    for (int idx = tid; idx < 384; idx += 128) {
        int c8 = idx & 3;
        int r  = idx >> 2;
        int sect = r >> 5, tok = r & 31;
        uint4 u = *reinterpret_cast<const uint4*>(
            qkv + (size_t)(bse + tok) * 768 + sect * 256 + hc + c8 * 8);
        float f[8];
        unpack8(u, f);
        if (sect == 0) {
#pragma unroll
            for (int i = 0; i < 8; i++) qs[tok][c8 * 8 + i] = f[i];
        } else if (sect == 1) {
#pragma unroll
            for (int i = 0; i < 8; i++) kT[c8 * 8 + i][tok] = f[i];
        } else {
#pragma unroll
            for (int i = 0; i < 8; i++) vs[tok][c8 * 8 + i] = f[i];
        }
    }
    __syncthreads();
    attn_core(qs, kT, vs, ps, tid, bse, hc, oh);
}

// Attention layer 0: qkv[n,w] = T[src(n,w)] + P[w]
__global__ void attn_kernel0(const __half* __restrict__ T,
                             __half* __restrict__ oh) {
    __shared__ float qs[32][36];
    __shared__ float kT[32][36];
    __shared__ float vs[32][36];
    __shared__ float ps[32][36];

    const int n   = blockIdx.x >> 3;
    const int h   = blockIdx.x & 7;
    const int tid = threadIdx.x;
    const int bse = n * 32;
    const int hc  = h * 32;
    const int s   = n & 511;
    const int b   = n >> 9;

    for (int idx = tid; idx < 384; idx += 128) {
        int c8 = idx & 3;
        int r  = idx >> 2;
        int sect = r >> 5, tok = r & 31;
        int src = s - tok; if (src < 0) src = 0;
        size_t off = (size_t)sect * 256 + hc + c8 * 8;
        uint4 u = *reinterpret_cast<const uint4*>(
            T + (size_t)(b * 512 + src) * 768 + off);
        const float* pq = g_pq + (size_t)tok * 768 + off;
        float f[8];
        unpack8(u, f);
#pragma unroll
        for (int i = 0; i < 8; i++) f[i] += pq[i];
        if (sect == 0) {
#pragma unroll
            for (int i = 0; i < 8; i++) qs[tok][c8 * 8 + i] = f[i];
        } else if (sect == 1) {
#pragma unroll
            for (int i = 0; i < 8; i++) kT[c8 * 8 + i][tok] = f[i];
        } else {
#pragma unroll
            for (int i = 0; i < 8; i++) vs[tok][c8 * 8 + i] = f[i];
        }
    }
    __syncthreads();
    attn_core(qs, kT, vs, ps, tid, bse, hc, oh);
}

// Attention layer 3 (minimal): kv = [NTOK x 512], q compact [NWIN x 256].
__global__ void attn_last(const __half* __restrict__ kv,
                          const __half* __restrict__ qc,
                          __half* __restrict__ oh) {
    __shared__ float ks[32][33];
    __shared__ float vs[32][33];
    __shared__ float qrow[32];
    __shared__ float pr[32];

    const int n   = blockIdx.x >> 3;
    const int h   = blockIdx.x & 7;
    const int tid = threadIdx.x;
    const int bse = n * 32;
    const int hc  = h * 32;

    for (int idx = tid; idx < 256; idx += 128) {
        int c8 = idx & 3;
        int r  = idx >> 2;
        int sect = r >> 5, tok = r & 31;
        uint4 u = *reinterpret_cast<const uint4*>(
            kv + (size_t)(bse + tok) * 512 + sect * 256 + hc + c8 * 8);
        float f[8];
        unpack8(u, f);
        float (*dst)[33] = sect ? vs : ks;
#pragma unroll
        for (int i = 0; i < 8; i++) dst[tok][c8 * 8 + i] = f[i];
    }
    if (tid < 32)
        qrow[tid] = __half2float(qc[(size_t)n * 256 + hc + tid]) * SCALE;
    __syncthreads();

    if (tid < 32) {
        float s = 0.f;
#pragma unroll
        for (int d = 0; d < 32; d++) s = fmaf(qrow[d], ks[tid][d], s);
        float mx = s;
#pragma unroll
        for (int o = 16; o > 0; o >>= 1)
            mx = fmaxf(mx, __shfl_xor_sync(0xffffffffu, mx, o));
        float e = __expf(s - mx);
        float sum = e;
#pragma unroll
        for (int o = 16; o > 0; o >>= 1)
            sum += __shfl_xor_sync(0xffffffffu, sum, o);
        pr[tid] = e / sum;
    }
    __syncthreads();

    if (tid < 32) {
        float o = 0.f;
#pragma unroll
        for (int j = 0; j < 32; j++) o = fmaf(pr[j], vs[j][tid], o);
        oh[(size_t)n * 256 + hc + tid] = __float2half(o);
    }
}

// ---------------------------------------------------------------------------
// LayerNorm body
// ---------------------------------------------------------------------------
__device__ __forceinline__ void ln_body(
    const float* vin, const float* gg, const float* bb, int c0, float* r)
{
    float s = 0.f;
#pragma unroll
    for (int j = 0; j < 8; j++) s += vin[j];
#pragma unroll
    for (int o = 16; o > 0; o >>= 1) s += __shfl_xor_sync(0xffffffffu, s, o);
    float mu = s * (1.f / 256.f);
    float s2 = 0.f;
#pragma unroll
    for (int j = 0; j < 8; j++) { float d = vin[j] - mu; s2 += d * d; }
#pragma unroll
    for (int o = 16; o > 0; o >>= 1) s2 += __shfl_xor_sync(0xffffffffu, s2, o);
    float rstd = rsqrtf(s2 * (1.f / 256.f) + EPS);
    float4 g0 = *reinterpret_cast<const float4*>(gg + c0);
    float4 g1 = *reinterpret_cast<const float4*>(gg + c0 + 4);
    float4 b0 = *reinterpret_cast<const float4*>(bb + c0);
    float4 b1 = *reinterpret_cast<const float4*>(bb + c0 + 4);
    r[0] = (vin[0] - mu) * rstd * g0.x + b0.x;
    r[1] = (vin[1] - mu) * rstd * g0.y + b0.y;
    r[2] = (vin[2] - mu) * rstd * g0.z + b0.z;
    r[3] = (vin[3] - mu) * rstd * g0.w + b0.w;
    r[4] = (vin[4] - mu) * rstd * g1.x + b1.x;
    r[5] = (vin[5] - mu) * rstd * g1.y + b1.y;
    r[6] = (vin[6] - mu) * rstd * g1.z + b1.z;
    r[7] = (vin[7] - mu) * rstd * g1.w + b1.w;
}

// Full add+LN on g_xh (fp16 residual, in-place; fp32 summation).
// WRITEQ: also copy w=31 rows to g_xq (compact layer-3 Q input).
template <bool WRITEQ>
__global__ void add_ln_kernel(const __half* __restrict__ y,
                              const float* __restrict__ gg,
                              const float* __restrict__ bb) {
    int warp  = threadIdx.x >> 5;
    int lane  = threadIdx.x & 31;
    int token = blockIdx.x * 8 + warp;
    int c0    = lane * 8;
    __half* xr = g_xh + (size_t)token * 256;

    uint4 yu = *reinterpret_cast<const uint4*>(y + (size_t)token * 256 + c0);
    uint4 xu = *reinterpret_cast<const uint4*>(xr + c0);
    float yv[8], xv[8], v[8];
    unpack8(yu, yv);
    unpack8(xu, xv);
#pragma unroll
    for (int j = 0; j < 8; j++) v[j] = xv[j] + yv[j];

    float r[8];
    ln_body(v, gg, bb, c0, r);
    uint4 o = make_uint4(cvt2h(r[0], r[1]), cvt2h(r[2], r[3]),
                         cvt2h(r[4], r[5]), cvt2h(r[6], r[7]));
    *reinterpret_cast<uint4*>(xr + c0) = o;
    if (WRITEQ && (token & 31) == 31)
        *reinterpret_cast<uint4*>(&g_xq[(size_t)(token >> 5) * 256 + c0]) = o;
}

// Compact add+LN (2048 rows): x from xin (fp16, arbitrary row stride), out fp16.
__global__ void add_ln_c(const __half* __restrict__ y,
                         const float* __restrict__ gg,
                         const float* __restrict__ bb,
                         const __half* __restrict__ xin, int xstride,
                         __half* __restrict__ outp) {
    int warp  = threadIdx.x >> 5;
    int lane  = threadIdx.x & 31;
    int token = blockIdx.x * 8 + warp;
    int c0    = lane * 8;

    uint4 yu = *reinterpret_cast<const uint4*>(y + (size_t)token * 256 + c0);
    uint4 xu = *reinterpret_cast<const uint4*>(
        xin + (size_t)token * xstride + c0);
    float yv[8], xv[8], v[8];
    unpack8(yu, yv);
    unpack8(xu, xv);
#pragma unroll
    for (int j = 0; j < 8; j++) v[j] = xv[j] + yv[j];

    float r[8];
    ln_body(v, gg, bb, c0, r);
    *reinterpret_cast<uint4*>(&outp[(size_t)token * 256 + c0]) =
        make_uint4(cvt2h(r[0], r[1]), cvt2h(r[2], r[3]),
                   cvt2h(r[4], r[5]), cvt2h(r[6], r[7]));
}

// ---------------------------------------------------------------------------
// Head: reads compact fp16 g_xc rows.
// ---------------------------------------------------------------------------
__global__ void head_kernel(const float* __restrict__ hw,
                            const float* __restrict__ hb,
                            float* __restrict__ out) {
    __shared__ float hws[32][257];
    __shared__ float xs[8][256];
    int tid = threadIdx.x;
    for (int idx = tid; idx < 32 * 256; idx += 256) {
        int c = idx >> 8, d = idx & 255;
        hws[c][d] = hw[idx];
    }
    int warp = tid >> 5, lane = tid & 31;
    int n = blockIdx.x * 8 + warp;
    {
        uint4 u = *reinterpret_cast<const uint4*>(
            g_xc + (size_t)n * 256 + lane * 8);
        float f[8];
        unpack8(u, f);
#pragma unroll
        for (int j = 0; j < 8; j++) xs[warp][lane * 8 + j] = f[j];
    }
    __syncthreads();

    float accum = hb[lane];
#pragma unroll 8
    for (int d = 0; d < 256; d++) accum = fmaf(xs[warp][d], hws[lane][d], accum);
    out[(size_t)n * 32 + lane] = accum;
}

// ---------------------------------------------------------------------------
// Launch
// ---------------------------------------------------------------------------
extern "C" void kernel_launch(void* const* d_in, const int* in_sizes, int n_in,
                              void* d_out, int out_size) {
    const float* X    = (const float*)d_in[0];
    const float* pos  = (const float*)d_in[3];
    const float* w_in = (const float*)d_in[4];
    const float* b_in = (const float*)d_in[5];
    const float* w_o  = (const float*)d_in[6];
    const float* b_o  = (const float*)d_in[7];
    const float* w1   = (const float*)d_in[8];
    const float* b1   = (const float*)d_in[9];
    const float* w2   = (const float*)d_in[10];
    const float* b2   = (const float*)d_in[11];
    const float* l1g  = (const float*)d_in[12];
    const float* l1b  = (const float*)d_in[13];
    const float* l2g  = (const float*)d_in[14];
    const float* l2b  = (const float*)d_in[15];
    const float* hw   = (const float*)d_in[16];
    const float* hb   = (const float*)d_in[17];
    float* out = (float*)d_out;

    void* p;
    cudaGetSymbolAddress(&p, g_qkv);  __half* qkv = (__half*)p;
    cudaGetSymbolAddress(&p, g_tmp);  __half* tmp = (__half*)p;
    cudaGetSymbolAddress(&p, g_xh);   __half* xh = (__half*)p;
    cudaGetSymbolAddress(&p, g_xq);   __half* xq = (__half*)p;
    cudaGetSymbolAddress(&p, g_qc);   __half* qc = (__half*)p;
    cudaGetSymbolAddress(&p, g_xc);   __half* xc = (__half*)p;
    cudaGetSymbolAddress(&p, g_ah);   __half* ah = (__half*)p;
    cudaGetSymbolAddress(&p, g_fh);   __half* fh = (__half*)p;
    cudaGetSymbolAddress(&p, g_xf);   __half* xf = (__half*)p;
    cudaGetSymbolAddress(&p, g_winh); __half* winh = (__half*)p;
    cudaGetSymbolAddress(&p, g_woh);  __half* woh = (__half*)p;
    cudaGetSymbolAddress(&p, g_w1h);  __half* w1h = (__half*)p;
    cudaGetSymbolAddress(&p, g_w2h);  __half* w2h = (__half*)p;

    cudaFuncSetAttribute((const void*)mma_gemm7<false>,
        cudaFuncAttributeMaxDynamicSharedMemorySize, GSMEM);
    cudaFuncSetAttribute((const void*)mma_gemm7<true>,
        cudaFuncAttributeMaxDynamicSharedMemorySize, GSMEM);

    const int PREP_N = 4*768*256 + 4*256*256 + 4*1024*256 + 4*256*1024 + NWIN*256;
    prep_all<<<(PREP_N + 255) / 256, 256>>>(w_in, w_o, w1, w2, X);
    pq_kernel<<<(32 * 768 + 255) / 256, 256>>>(pos, w_in);
    gather_kernel<<<NTOK * 64 / 256, 256>>>(X, pos);

    for (int l = 0; l < 4; l++) {
        if (l == 0) {
            mma_gemm7<false><<<dim3(6, 16), 256, GSMEM>>>(
                xf, winh, b_in, qkv, 256, 768);
            attn_kernel0<<<NWIN * 8, 128>>>(qkv, ah);
        } else if (l < 3) {
            mma_gemm7<false><<<dim3(6, 512), 256, GSMEM>>>(
                xh, winh + (size_t)l * 768 * 256,
                b_in + (size_t)l * 768, qkv, 256, 768);
            attn_kernel3<<<NWIN * 8, 128>>>(qkv, ah);
        } else {
            mma_gemm7<false><<<dim3(4, 512), 256, GSMEM>>>(
                xh, winh + (size_t)3 * 768 * 256 + 256 * 256,
                b_in + 3 * 768 + 256, qkv, 256, 512);
            mma_gemm7<false><<<dim3(2, 16), 256, GSMEM>>>(
                xq, winh + (size_t)3 * 768 * 256,
                b_in + 3 * 768, qc, 256, 256);
            attn_last<<<NWIN * 8, 128>>>(qkv, qc, ah);
        }
        if (l < 3) {
            mma_gemm7<false><<<dim3(2, 512), 256, GSMEM>>>(
                ah, woh + (size_t)l * 256 * 256,
                b_o + (size_t)l * 256, tmp, 256, 256);
            add_ln_kernel<false><<<NTOK / 8, 256>>>(
                tmp, l1g + (size_t)l * 256, l1b + (size_t)l * 256);
            mma_gemm7<true><<<dim3(8, 512), 256, GSMEM>>>(
                xh, w1h + (size_t)l * 1024 * 256,
                b1 + (size_t)l * 1024, fh, 256, 1024);
            mma_gemm7<false><<<dim3(2, 512), 256, GSMEM>>>(
                fh, w2h + (size_t)l * 256 * 1024,
                b2 + (size_t)l * 256, tmp, 1024, 256);
            if (l == 2)
                add_ln_kernel<true><<<NTOK / 8, 256>>>(
                    tmp, l2g + (size_t)l * 256, l2b + (size_t)l * 256);
            else
                add_ln_kernel<false><<<NTOK / 8, 256>>>(
                    tmp, l2g + (size_t)l * 256, l2b + (size_t)l * 256);
        } else {
            mma_gemm7<false><<<dim3(2, 16), 256, GSMEM>>>(
                ah, woh + (size_t)3 * 256 * 256,
                b_o + 3 * 256, tmp, 256, 256);
            add_ln_c<<<NWIN / 8, 256>>>(
                tmp, l1g + (size_t)3 * 256, l1b + (size_t)3 * 256,
                xq, 256, xc);
            mma_gemm7<true><<<dim3(8, 16), 256, GSMEM>>>(
                xc, w1h + (size_t)3 * 1024 * 256,
                b1 + (size_t)3 * 1024, fh, 256, 1024);
            mma_gemm7<false><<<dim3(2, 16), 256, GSMEM>>>(
                fh, w2h + (size_t)3 * 256 * 1024,
                b2 + 3 * 256, tmp, 1024, 256);
            add_ln_c<<<NWIN / 8, 256>>>(
                tmp, l2g + (size_t)3 * 256, l2b + (size_t)3 * 256,
                xc, 256, xc);
        }
    }

    head_kernel<<<NWIN / 8, 256>>>(hw, hb, out);
}